// round 2
// baseline (speedup 1.0000x reference)
#include <cuda_runtime.h>
#include <cuda_bf16.h>

// Problem constants (fixed shapes)
#define BATCH   128
#define SEQLEN  16384
#define NBANDS  20
#define TAPS    513
#define PAD     512                 // padlen = TAPS-1
#define EXTLEN  (SEQLEN + 2*PAD)    // 17408

// Tile config for main conv kernel
#define THREADS 256
#define POS     4                   // outputs per thread
#define TI      (THREADS*POS)       // 1024 outputs per CTA
#define WIN     (TI + 2*PAD)        // 2048 window floats
#define SHPAD   8                   // zero pad for float4 overrun
#define C2MAX   1040                // >= 2*512+4, padded

// Scratch (static device globals; no runtime allocation)
__device__ float g_ext[BATCH * EXTLEN];     // odd-extended signals
__device__ float g_c[NBANDS * TAPS];        // per-band autocorrelation c[m], m=0..512
__device__ int   g_M[NBANDS];               // per-band half length M = T-1 (last nonzero tap)

// ---------------------------------------------------------------------------
// Kernel 1: build odd extension  ext = [2x0 - x[512-j] | x | 2x_{L-1} - x[L-2-j]]
// ---------------------------------------------------------------------------
__global__ void build_ext_kernel(const float* __restrict__ x) {
    int idx = blockIdx.x * blockDim.x + threadIdx.x;
    if (idx >= BATCH * EXTLEN) return;
    int b = idx / EXTLEN;
    int j = idx - b * EXTLEN;
    const float* xb = x + b * SEQLEN;
    float v;
    if (j < PAD) {
        v = 2.0f * xb[0] - xb[PAD - j];
    } else if (j < PAD + SEQLEN) {
        v = xb[j - PAD];
    } else {
        int jr = j - (PAD + SEQLEN);
        v = 2.0f * xb[SEQLEN - 1] - xb[SEQLEN - 2 - jr];
    }
    g_ext[idx] = v;
}

// ---------------------------------------------------------------------------
// Kernel 2: per-band autocorrelation c[m] = sum_j b[j]*b[j+m], and M = last
// nonzero tap index (c[m] == 0 for m > M).
// One block per band.
// ---------------------------------------------------------------------------
__global__ void autocorr_kernel(const float* __restrict__ kern) {
    int band = blockIdx.x;
    const float* kb = kern + band * TAPS;
    __shared__ float sk[TAPS];
    __shared__ int s_last;
    int tid = threadIdx.x;
    for (int i = tid; i < TAPS; i += blockDim.x) sk[i] = kb[i];
    if (tid == 0) s_last = 0;
    __syncthreads();
    // last nonzero tap (thread 0, serial scan: trivial cost)
    if (tid == 0) {
        int last = 0;
        for (int i = 0; i < TAPS; i++) if (sk[i] != 0.0f) last = i;
        s_last = last;
        g_M[band] = last;
    }
    __syncthreads();
    int M = s_last;
    for (int m = tid; m < TAPS; m += blockDim.x) {
        float s = 0.0f;
        if (m <= M) {
            int jmax = M - m;   // taps beyond M are zero
            for (int j = 0; j <= jmax; j++) s = fmaf(sk[j], sk[j + m], s);
        }
        g_c[band * TAPS + m] = s;
    }
}

// ---------------------------------------------------------------------------
// Kernel 3: main correlation.
// out[b, band, i] = sum_{m=-M}^{M} c[m] * ext[b][PAD + i + m]
// Each CTA: one (batch, tile of 1024 positions), loops over all 20 bands.
// Thread t owns 4 consecutive outputs. Inner loop: per 4 taps -> 3 LDS.128
// (window x2 + c broadcast) + 16 FFMA. Conflict-free (16B/thread stride).
// ---------------------------------------------------------------------------
__global__ __launch_bounds__(THREADS) void conv_kernel(float* __restrict__ out) {
    __shared__ float sh[WIN + SHPAD];
    __shared__ float c2[C2MAX];

    const int tid = threadIdx.x;
    const int cta = blockIdx.x;
    const int tilesPerBatch = SEQLEN / TI;          // 16
    const int tile  = cta & (tilesPerBatch - 1);
    const int batch = cta / tilesPerBatch;
    const int tileStart = tile * TI;

    // Load window ext[batch][tileStart .. tileStart + WIN) via float4
    {
        const float4* src = reinterpret_cast<const float4*>(g_ext + batch * EXTLEN + tileStart);
        float4* dst = reinterpret_cast<float4*>(sh);
        #pragma unroll
        for (int i = 0; i < WIN / 4 / THREADS; i++)
            dst[tid + i * THREADS] = src[tid + i * THREADS];
        if (tid < SHPAD) sh[WIN + tid] = 0.0f;      // zero tail pad
    }

    for (int band = 0; band < NBANDS; band++) {
        const int M  = g_M[band];
        const int Mp = (M + 3) & ~3;                // round up to mult of 4
        const int U  = 2 * Mp + 4;                  // padded tap count, mult of 4
        const int off = PAD - Mp;                   // >= 0, mult of 4

        __syncthreads();                            // previous band done with c2
        // Fill c2[u] = c[|u - Mp|] (0 outside [-M, M])
        const float* cb = g_c + band * TAPS;
        for (int u = tid; u < U; u += THREADS) {
            int m = u - Mp;
            int am = (m < 0) ? -m : m;
            c2[u] = (am <= M) ? cb[am] : 0.0f;
        }
        __syncthreads();

        float4 acc = make_float4(0.0f, 0.0f, 0.0f, 0.0f);
        const float4* w4 = reinterpret_cast<const float4*>(sh + (tid << 2) + off);
        const float4* c4 = reinterpret_cast<const float4*>(c2);
        const int n4 = U >> 2;

        #pragma unroll 2
        for (int q = 0; q < n4; q++) {
            float4 cv = c4[q];
            float4 a  = w4[q];
            float4 b2 = w4[q + 1];
            acc.x = fmaf(cv.x, a.x, acc.x);
            acc.x = fmaf(cv.y, a.y, acc.x);
            acc.x = fmaf(cv.z, a.z, acc.x);
            acc.x = fmaf(cv.w, a.w, acc.x);

            acc.y = fmaf(cv.x, a.y, acc.y);
            acc.y = fmaf(cv.y, a.z, acc.y);
            acc.y = fmaf(cv.z, a.w, acc.y);
            acc.y = fmaf(cv.w, b2.x, acc.y);

            acc.z = fmaf(cv.x, a.z, acc.z);
            acc.z = fmaf(cv.y, a.w, acc.z);
            acc.z = fmaf(cv.z, b2.x, acc.z);
            acc.z = fmaf(cv.w, b2.y, acc.z);

            acc.w = fmaf(cv.x, a.w, acc.w);
            acc.w = fmaf(cv.y, b2.x, acc.w);
            acc.w = fmaf(cv.z, b2.y, acc.w);
            acc.w = fmaf(cv.w, b2.z, acc.w);
        }

        float4* op = reinterpret_cast<float4*>(
            out + ((size_t)(batch * NBANDS + band) << 14) + tileStart + (tid << 2));
        *op = acc;
    }
}

extern "C" void kernel_launch(void* const* d_in, const int* in_sizes, int n_in,
                              void* d_out, int out_size) {
    (void)in_sizes; (void)n_in; (void)out_size;
    const float* x    = (const float*)d_in[0];
    const float* kern = (const float*)d_in[1];
    // d_in[2] = padlen (always 512 for this problem)

    int extElems = BATCH * EXTLEN;
    build_ext_kernel<<<(extElems + 255) / 256, 256>>>(x);
    autocorr_kernel<<<NBANDS, 256>>>(kern);
    conv_kernel<<<BATCH * (SEQLEN / TI), THREADS>>>((float*)d_out);
}